// round 5
// baseline (speedup 1.0000x reference)
#include <cuda_runtime.h>
#include <cstdint>

#define NODE_EMB 128
#define EDGE_EMB 16
#define D_IN     160      // 128 + 2*16
#define N_MAX    100000
#define E_MAX    3400000

#define TILE_N   128
#define THREADS  512
#define AS_STRIDE 132

#define SCAN_T   512
#define SCAN_E   4
#define SCAN_BLOCK (SCAN_T * SCAN_E)   // 2048
#define MAX_NB   128

// ---------------- device scratch (no cudaMalloc allowed) ----------------
__device__ float    g_rec [N_MAX * EDGE_EMB];   // per-node mean (written once)
__device__ float    g_sent[N_MAX * EDGE_EMB];
__device__ unsigned g_hist[2 * N_MAX];
__device__ unsigned g_off [2 * N_MAX + 1];      // exclusive scan + sentinel
__device__ unsigned g_cur [2 * N_MAX];          // scatter cursors
__device__ unsigned g_bsum[MAX_NB];
__device__ int      g_sorted[2 * E_MAX];        // edge ids sorted by bin

// ---------------- packed f32x2 helpers (sm_100+) ----------------
__device__ __forceinline__ unsigned long long pack2(float lo, float hi) {
    unsigned long long r;
    asm("mov.b64 %0, {%1, %2};" : "=l"(r) : "f"(lo), "f"(hi));
    return r;
}
__device__ __forceinline__ unsigned long long bcast2(float v) {
    unsigned long long r;
    asm("mov.b64 %0, {%1, %1};" : "=l"(r) : "f"(v));
    return r;
}
__device__ __forceinline__ void fma2(unsigned long long& d,
                                     unsigned long long a,
                                     unsigned long long b) {
    asm("fma.rn.f32x2 %0, %1, %2, %0;" : "+l"(d) : "l"(a), "l"(b));
}
__device__ __forceinline__ void unpack2(unsigned long long v, float& lo, float& hi) {
    asm("mov.b64 {%0, %1}, %2;" : "=f"(lo), "=f"(hi) : "l"(v));
}

// ---------------- sort pipeline ----------------
__global__ void zero_hist_kernel(int ntotal) {
    int t = blockIdx.x * blockDim.x + threadIdx.x;
    if (t < ntotal) g_hist[t] = 0u;
}

__global__ void hist_kernel(const int* __restrict__ ei, int E, int N) {
    int e = blockIdx.x * blockDim.x + threadIdx.x;
    if (e >= E) return;
    atomicAdd(&g_hist[ei[e]], 1u);           // receiver bins [0, N)
    atomicAdd(&g_hist[N + ei[E + e]], 1u);   // sender bins [N, 2N)
}

__global__ void scanA_kernel(int ntotal) {
    __shared__ unsigned wsum[16];
    int t = threadIdx.x, b = blockIdx.x;
    int lane = t & 31, wid = t >> 5;
    int base = b * SCAN_BLOCK + t * SCAN_E;
    unsigned v[SCAN_E]; unsigned s = 0;
    #pragma unroll
    for (int j = 0; j < SCAN_E; ++j) {
        v[j] = (base + j < ntotal) ? g_hist[base + j] : 0u;
        s += v[j];
    }
    unsigned inc = s;
    #pragma unroll
    for (int d = 1; d < 32; d <<= 1) {
        unsigned u = __shfl_up_sync(0xFFFFFFFFu, inc, d);
        if (lane >= d) inc += u;
    }
    if (lane == 31) wsum[wid] = inc;
    __syncthreads();
    if (wid == 0) {
        unsigned w = (lane < 16) ? wsum[lane] : 0u;
        unsigned wi = w;
        #pragma unroll
        for (int d = 1; d < 16; d <<= 1) {
            unsigned u = __shfl_up_sync(0xFFFFFFFFu, wi, d);
            if (lane >= d) wi += u;
        }
        if (lane < 16) wsum[lane] = wi - w;     // exclusive warp offsets
        if (lane == 15) g_bsum[b] = wi;          // block total
    }
    __syncthreads();
    unsigned run = inc - s + wsum[wid];          // exclusive prefix for this thread
    #pragma unroll
    for (int j = 0; j < SCAN_E; ++j) {
        if (base + j < ntotal) g_off[base + j] = run;
        run += v[j];
    }
}

__global__ void scanB_kernel(int nb, int ntotal) {
    __shared__ unsigned wsum[4];
    int t = threadIdx.x, lane = t & 31, wid = t >> 5;
    unsigned v = (t < nb) ? g_bsum[t] : 0u;
    unsigned inc = v;
    #pragma unroll
    for (int d = 1; d < 32; d <<= 1) {
        unsigned u = __shfl_up_sync(0xFFFFFFFFu, inc, d);
        if (lane >= d) inc += u;
    }
    if (lane == 31) wsum[wid] = inc;
    __syncthreads();
    if (wid == 0) {
        unsigned w = (lane < 4) ? wsum[lane] : 0u;
        unsigned wi = w;
        #pragma unroll
        for (int d = 1; d < 4; d <<= 1) {
            unsigned u = __shfl_up_sync(0xFFFFFFFFu, wi, d);
            if (lane >= d) wi += u;
        }
        if (lane < 4) wsum[lane] = wi - w;
    }
    __syncthreads();
    unsigned excl = inc - v + wsum[wid];
    if (t < nb) g_bsum[t] = excl;
    if (t == 127) g_off[ntotal] = excl + v;      // grand total (padded lanes add 0)
}

__global__ void scanC_kernel(int ntotal) {
    unsigned add = g_bsum[blockIdx.x];
    int base = blockIdx.x * SCAN_BLOCK + threadIdx.x * SCAN_E;
    #pragma unroll
    for (int j = 0; j < SCAN_E; ++j) {
        int idx = base + j;
        if (idx < ntotal) {
            unsigned v = g_off[idx] + add;
            g_off[idx] = v;
            g_cur[idx] = v;
        }
    }
}

__global__ void scatter_ids_kernel(const int* __restrict__ ei, int E, int N) {
    int e = blockIdx.x * blockDim.x + threadIdx.x;
    if (e >= E) return;
    int r = ei[e];
    int c = ei[E + e];
    unsigned pr = atomicAdd(&g_cur[r], 1u);
    g_sorted[pr] = e;
    unsigned ps = atomicAdd(&g_cur[N + c], 1u);
    g_sorted[ps] = e;
}

// One warp per bin. Lanes: f = lane&15 -> feature, q = lane>>4 -> slot parity.
// ILP-4 per lane => 8 edge rows in flight per warp (hide DRAM latency).
__global__ __launch_bounds__(256)
void gather_kernel(const float* __restrict__ edge_attr, int N, int nbins) {
    int w = (blockIdx.x * blockDim.x + threadIdx.x) >> 5;
    if (w >= nbins) return;
    int lane = threadIdx.x & 31;
    int f = lane & 15;
    int q = lane >> 4;
    unsigned start = g_off[w], end = g_off[w + 1];
    float a0 = 0.f, a1 = 0.f, a2 = 0.f, a3 = 0.f;
    unsigned i = start + q;
    for (; i + 6 < end; i += 8) {
        int e0 = g_sorted[i];
        int e1 = g_sorted[i + 2];
        int e2 = g_sorted[i + 4];
        int e3 = g_sorted[i + 6];
        a0 += edge_attr[(size_t)e0 * EDGE_EMB + f];
        a1 += edge_attr[(size_t)e1 * EDGE_EMB + f];
        a2 += edge_attr[(size_t)e2 * EDGE_EMB + f];
        a3 += edge_attr[(size_t)e3 * EDGE_EMB + f];
    }
    for (; i < end; i += 2)
        a0 += edge_attr[(size_t)g_sorted[i] * EDGE_EMB + f];
    a0 = (a0 + a1) + (a2 + a3);
    a0 += __shfl_xor_sync(0xFFFFFFFFu, a0, 16);
    if (lane < 16) {
        float cnt = (float)(end - start);
        float m = a0 / fmaxf(cnt, 1.f);
        if (w < N) g_rec [(size_t)w * EDGE_EMB + f] = m;
        else       g_sent[(size_t)(w - N) * EDGE_EMB + f] = m;
    }
}

// ---------------- fused concat + MLP (R4 transposed node-pair scheme) ----------------
__global__ __launch_bounds__(THREADS, 1)
void mlp_kernel(const float* __restrict__ x,
                const float* __restrict__ W1,
                const float* __restrict__ b1,
                const float* __restrict__ W2,
                const float* __restrict__ b2,
                float* __restrict__ out,
                int N) {
    extern __shared__ float smem_f[];
    float* As  = smem_f;                        // [D_IN][AS_STRIDE] transposed A / h
    float* W1s = As + D_IN * AS_STRIDE;
    float* W2s = W1s + D_IN * NODE_EMB;

    int tid = threadIdx.x;
    int tx = tid & 31;
    int ty = tid >> 5;
    int node0 = blockIdx.x * TILE_N;

    for (int i = tid; i < (D_IN * NODE_EMB) / 4; i += THREADS)
        reinterpret_cast<float4*>(W1s)[i] = reinterpret_cast<const float4*>(W1)[i];
    for (int i = tid; i < (NODE_EMB * NODE_EMB) / 4; i += THREADS)
        reinterpret_cast<float4*>(W2s)[i] = reinterpret_cast<const float4*>(W2)[i];

    // Stage A^T: concat(x, rec_mean, sent_mean), transposed [k][node]
    for (int idx = tid; idx < TILE_N * D_IN; idx += THREADS) {
        int nl = idx / D_IN;
        int k  = idx - nl * D_IN;
        int n  = node0 + nl;
        float v = 0.f;
        if (n < N) {
            if (k < NODE_EMB)                     v = x[(size_t)n * NODE_EMB + k];
            else if (k < NODE_EMB + EDGE_EMB)     v = g_rec [(size_t)n * EDGE_EMB + (k - NODE_EMB)];
            else                                  v = g_sent[(size_t)n * EDGE_EMB + (k - NODE_EMB - EDGE_EMB)];
        }
        As[k * AS_STRIDE + nl] = v;
    }
    __syncthreads();

    // ---- Phase 1: h = A @ W1 + b1 ----
    unsigned long long acc[4][4];
    #pragma unroll
    for (int cc = 0; cc < 4; ++cc) {
        unsigned long long bb = bcast2(b1[tx + 32 * cc]);
        #pragma unroll
        for (int j = 0; j < 4; ++j) acc[j][cc] = bb;
    }
    #pragma unroll 4
    for (int k = 0; k < D_IN; ++k) {
        const float* ar = &As[k * AS_STRIDE + ty * 8];
        ulonglong2 a01 = *reinterpret_cast<const ulonglong2*>(ar);
        ulonglong2 a23 = *reinterpret_cast<const ulonglong2*>(ar + 4);
        const float* wr = &W1s[k * NODE_EMB + tx];
        #pragma unroll
        for (int cc = 0; cc < 4; ++cc) {
            unsigned long long wd = bcast2(wr[32 * cc]);
            fma2(acc[0][cc], a01.x, wd);
            fma2(acc[1][cc], a01.y, wd);
            fma2(acc[2][cc], a23.x, wd);
            fma2(acc[3][cc], a23.y, wd);
        }
    }
    __syncthreads();

    // LeakyReLU + store h^T
    #pragma unroll
    for (int cc = 0; cc < 4; ++cc) {
        int c = tx + 32 * cc;
        #pragma unroll
        for (int j = 0; j < 4; ++j) {
            float v0, v1;
            unpack2(acc[j][cc], v0, v1);
            v0 = (v0 >= 0.f) ? v0 : 0.01f * v0;
            v1 = (v1 >= 0.f) ? v1 : 0.01f * v1;
            *reinterpret_cast<unsigned long long*>(&As[c * AS_STRIDE + ty * 8 + 2 * j])
                = pack2(v0, v1);
        }
    }
    __syncthreads();

    // ---- Phase 2: out = h @ W2 + b2 ----
    #pragma unroll
    for (int cc = 0; cc < 4; ++cc) {
        unsigned long long bb = bcast2(b2[tx + 32 * cc]);
        #pragma unroll
        for (int j = 0; j < 4; ++j) acc[j][cc] = bb;
    }
    #pragma unroll 4
    for (int k = 0; k < NODE_EMB; ++k) {
        const float* ar = &As[k * AS_STRIDE + ty * 8];
        ulonglong2 a01 = *reinterpret_cast<const ulonglong2*>(ar);
        ulonglong2 a23 = *reinterpret_cast<const ulonglong2*>(ar + 4);
        const float* wr = &W2s[k * NODE_EMB + tx];
        #pragma unroll
        for (int cc = 0; cc < 4; ++cc) {
            unsigned long long wd = bcast2(wr[32 * cc]);
            fma2(acc[0][cc], a01.x, wd);
            fma2(acc[1][cc], a01.y, wd);
            fma2(acc[2][cc], a23.x, wd);
            fma2(acc[3][cc], a23.y, wd);
        }
    }

    #pragma unroll
    for (int j = 0; j < 4; ++j) {
        int n0i = node0 + ty * 8 + 2 * j;
        #pragma unroll
        for (int cc = 0; cc < 4; ++cc) {
            float v0, v1;
            unpack2(acc[j][cc], v0, v1);
            int c = tx + 32 * cc;
            if (n0i < N)     out[(size_t)n0i * NODE_EMB + c]       = v0;
            if (n0i + 1 < N) out[(size_t)(n0i + 1) * NODE_EMB + c] = v1;
        }
    }
}

// ---------------- launch ----------------
extern "C" void kernel_launch(void* const* d_in, const int* in_sizes, int n_in,
                              void* d_out, int out_size) {
    const float* x          = (const float*)d_in[0];
    const int*   edge_index = (const int*)  d_in[1];
    const float* edge_attr  = (const float*)d_in[2];
    const float* W1         = (const float*)d_in[3];
    const float* b1         = (const float*)d_in[4];
    const float* W2         = (const float*)d_in[5];
    const float* b2         = (const float*)d_in[6];
    float* out = (float*)d_out;

    int N = in_sizes[0] / NODE_EMB;
    int E = in_sizes[2] / EDGE_EMB;
    int ntotal = 2 * N;                              // bins: [0,N) rec, [N,2N) sent
    int NB = (ntotal + SCAN_BLOCK - 1) / SCAN_BLOCK; // 98 for N=100k (<= MAX_NB)

    zero_hist_kernel<<<(ntotal + 1023) / 1024, 1024>>>(ntotal);
    hist_kernel<<<(E + 255) / 256, 256>>>(edge_index, E, N);
    scanA_kernel<<<NB, SCAN_T>>>(ntotal);
    scanB_kernel<<<1, 128>>>(NB, ntotal);
    scanC_kernel<<<NB, SCAN_T>>>(ntotal);
    scatter_ids_kernel<<<(E + 255) / 256, 256>>>(edge_index, E, N);
    gather_kernel<<<(ntotal + 7) / 8, 256>>>(edge_attr, N, ntotal);

    const int smem_bytes = (D_IN * AS_STRIDE + D_IN * NODE_EMB + NODE_EMB * NODE_EMB) * 4;
    cudaFuncSetAttribute(mlp_kernel, cudaFuncAttributeMaxDynamicSharedMemorySize, smem_bytes);
    mlp_kernel<<<(N + TILE_N - 1) / TILE_N, THREADS, smem_bytes>>>(
        x, W1, b1, W2, b2, out, N);
}

// round 6
// speedup vs baseline: 1.1730x; 1.1730x over previous
#include <cuda_runtime.h>
#include <cstdint>

#define NODE_EMB 128
#define EDGE_EMB 16
#define D_IN     160
#define N_MAX    100000
#define TILE_N   128
#define THREADS  512
#define AS_STRIDE 132
#define NSC      64          // scatter CTAs inside fused kernel

// ---------------- device scratch ----------------
__device__ float g_rec [N_MAX * EDGE_EMB];
__device__ float g_sent[N_MAX * EDGE_EMB];
__device__ float g_rcnt[N_MAX];
__device__ float g_scnt[N_MAX];
__device__ float g_hp  [N_MAX * NODE_EMB];   // partial h = x@W1a + b1

// ---------------- packed f32x2 helpers ----------------
__device__ __forceinline__ unsigned long long pack2(float lo, float hi) {
    unsigned long long r;
    asm("mov.b64 %0, {%1, %2};" : "=l"(r) : "f"(lo), "f"(hi));
    return r;
}
__device__ __forceinline__ unsigned long long bcast2(float v) {
    unsigned long long r;
    asm("mov.b64 %0, {%1, %1};" : "=l"(r) : "f"(v));
    return r;
}
__device__ __forceinline__ void fma2(unsigned long long& d,
                                     unsigned long long a,
                                     unsigned long long b) {
    asm("fma.rn.f32x2 %0, %1, %2, %0;" : "+l"(d) : "l"(a), "l"(b));
}
__device__ __forceinline__ void unpack2(unsigned long long v, float& lo, float& hi) {
    asm("mov.b64 {%0, %1}, %2;" : "=f"(lo), "=f"(hi) : "l"(v));
}
__device__ __forceinline__ void red4(float* p, float4 v) {
    asm volatile("red.global.add.v4.f32 [%0], {%1, %2, %3, %4};"
                 :: "l"(p), "f"(v.x), "f"(v.y), "f"(v.z), "f"(v.w) : "memory");
}

// ---------------- kernel 1: zero accumulators ----------------
__global__ void zero_kernel(int N) {
    int stride = gridDim.x * blockDim.x;
    int t = blockIdx.x * blockDim.x + threadIdx.x;
    int total4 = N * EDGE_EMB / 4;
    float4 z = make_float4(0.f, 0.f, 0.f, 0.f);
    for (int i = t; i < total4; i += stride) {
        reinterpret_cast<float4*>(g_rec)[i]  = z;
        reinterpret_cast<float4*>(g_sent)[i] = z;
    }
    for (int i = t; i < N; i += stride) {
        g_rcnt[i] = 0.f;
        g_scnt[i] = 0.f;
    }
}

// ---------------- kernel 2: heterogeneous scatter + partial-MLP ----------------
// blockIdx < NSC: grid-stride dual scatter-sum (L2-ALU-bound, ~240us, 64 SMs)
// blockIdx >= NSC: hp = x @ W1[0:128] + b1 per 128-node tile (FMA-bound) — runs
// concurrently on the remaining SMs, hidden under the scatter.
__global__ __launch_bounds__(THREADS, 1)
void fused_kernel(const float* __restrict__ x,
                  const int* __restrict__ ei,
                  const float4* __restrict__ attr4,
                  const float* __restrict__ W1,
                  const float* __restrict__ b1,
                  int E, int N) {
    if (blockIdx.x < NSC) {
        int t = blockIdx.x * THREADS + threadIdx.x;
        int stride = NSC * THREADS;
        for (int e = t; e < E; e += stride) {
            int row = ei[e];
            int col = ei[E + e];
            float4 v0 = attr4[(size_t)e * 4 + 0];
            float4 v1 = attr4[(size_t)e * 4 + 1];
            float4 v2 = attr4[(size_t)e * 4 + 2];
            float4 v3 = attr4[(size_t)e * 4 + 3];
            float* pr = &g_rec [(size_t)row * EDGE_EMB];
            float* ps = &g_sent[(size_t)col * EDGE_EMB];
            red4(pr + 0, v0); red4(pr + 4, v1); red4(pr + 8, v2); red4(pr + 12, v3);
            red4(ps + 0, v0); red4(ps + 4, v1); red4(ps + 8, v2); red4(ps + 12, v3);
            atomicAdd(&g_rcnt[row], 1.0f);
            atomicAdd(&g_scnt[col], 1.0f);
        }
        return;
    }

    // ---- partial MLP ----
    extern __shared__ float smem_f[];
    float* As  = smem_f;                          // x^T [128][AS_STRIDE]
    float* W1s = As + NODE_EMB * AS_STRIDE;       // W1 rows 0..127 [128][128]

    int tid = threadIdx.x;
    int tx = tid & 31;
    int ty = tid >> 5;
    int node0 = (blockIdx.x - NSC) * TILE_N;

    for (int i = tid; i < (NODE_EMB * NODE_EMB) / 4; i += THREADS)
        reinterpret_cast<float4*>(W1s)[i] = reinterpret_cast<const float4*>(W1)[i];

    for (int idx = tid; idx < TILE_N * NODE_EMB; idx += THREADS) {
        int nl = idx >> 7;          // /128
        int k  = idx & 127;
        int n  = node0 + nl;
        As[k * AS_STRIDE + nl] = (n < N) ? x[(size_t)n * NODE_EMB + k] : 0.f;
    }
    __syncthreads();

    unsigned long long acc[4][4];
    #pragma unroll
    for (int cc = 0; cc < 4; ++cc) {
        unsigned long long bb = bcast2(b1[tx + 32 * cc]);
        #pragma unroll
        for (int j = 0; j < 4; ++j) acc[j][cc] = bb;
    }
    #pragma unroll 4
    for (int k = 0; k < NODE_EMB; ++k) {
        const float* ar = &As[k * AS_STRIDE + ty * 8];
        ulonglong2 a01 = *reinterpret_cast<const ulonglong2*>(ar);
        ulonglong2 a23 = *reinterpret_cast<const ulonglong2*>(ar + 4);
        const float* wr = &W1s[k * NODE_EMB + tx];
        #pragma unroll
        for (int cc = 0; cc < 4; ++cc) {
            unsigned long long wd = bcast2(wr[32 * cc]);
            fma2(acc[0][cc], a01.x, wd);
            fma2(acc[1][cc], a01.y, wd);
            fma2(acc[2][cc], a23.x, wd);
            fma2(acc[3][cc], a23.y, wd);
        }
    }

    #pragma unroll
    for (int j = 0; j < 4; ++j) {
        int n0i = node0 + ty * 8 + 2 * j;
        #pragma unroll
        for (int cc = 0; cc < 4; ++cc) {
            float v0, v1;
            unpack2(acc[j][cc], v0, v1);
            int c = tx + 32 * cc;
            if (n0i < N)     g_hp[(size_t)n0i * NODE_EMB + c]       = v0;
            if (n0i + 1 < N) g_hp[(size_t)(n0i + 1) * NODE_EMB + c] = v1;
        }
    }
}

// ---------------- kernel 3: finish — mean contribution + LeakyReLU + phase 2 ----------------
__global__ __launch_bounds__(THREADS, 1)
void finish_kernel(const float* __restrict__ W1,
                   const float* __restrict__ W2,
                   const float* __restrict__ b2,
                   float* __restrict__ out,
                   int N) {
    extern __shared__ float smem_f[];
    float* Hs   = smem_f;                              // h^T [128][AS_STRIDE]
    float* Ms   = Hs + NODE_EMB * AS_STRIDE;           // means^T [32][AS_STRIDE]
    float* W1bs = Ms + 2 * EDGE_EMB * AS_STRIDE;       // W1 rows 128..159 [32][128]
    float* W2s  = W1bs + 2 * EDGE_EMB * NODE_EMB;      // [128][128]

    int tid = threadIdx.x;
    int tx = tid & 31;
    int ty = tid >> 5;
    int node0 = blockIdx.x * TILE_N;

    for (int i = tid; i < (2 * EDGE_EMB * NODE_EMB) / 4; i += THREADS)
        reinterpret_cast<float4*>(W1bs)[i] =
            reinterpret_cast<const float4*>(W1 + NODE_EMB * NODE_EMB)[i];
    for (int i = tid; i < (NODE_EMB * NODE_EMB) / 4; i += THREADS)
        reinterpret_cast<float4*>(W2s)[i] = reinterpret_cast<const float4*>(W2)[i];

    // Stage means^T [k][node], k in 0..31 (rec 0..15, sent 16..31)
    for (int idx = tid; idx < TILE_N * 2 * EDGE_EMB; idx += THREADS) {
        int nl = idx >> 5;          // /32
        int k  = idx & 31;
        int n  = node0 + nl;
        float v = 0.f;
        if (n < N) {
            if (k < EDGE_EMB) v = g_rec [(size_t)n * EDGE_EMB + k]              / fmaxf(g_rcnt[n], 1.f);
            else              v = g_sent[(size_t)n * EDGE_EMB + (k - EDGE_EMB)] / fmaxf(g_scnt[n], 1.f);
        }
        Ms[k * AS_STRIDE + nl] = v;
    }
    __syncthreads();

    // Load hp into accumulators
    unsigned long long acc[4][4];
    #pragma unroll
    for (int j = 0; j < 4; ++j) {
        int n0i = node0 + ty * 8 + 2 * j;
        #pragma unroll
        for (int cc = 0; cc < 4; ++cc) {
            int c = tx + 32 * cc;
            float lo = (n0i < N)     ? g_hp[(size_t)n0i * NODE_EMB + c]       : 0.f;
            float hi = (n0i + 1 < N) ? g_hp[(size_t)(n0i + 1) * NODE_EMB + c] : 0.f;
            acc[j][cc] = pack2(lo, hi);
        }
    }

    // Mean-driven k-iterations (32)
    #pragma unroll 4
    for (int k = 0; k < 2 * EDGE_EMB; ++k) {
        const float* ar = &Ms[k * AS_STRIDE + ty * 8];
        ulonglong2 a01 = *reinterpret_cast<const ulonglong2*>(ar);
        ulonglong2 a23 = *reinterpret_cast<const ulonglong2*>(ar + 4);
        const float* wr = &W1bs[k * NODE_EMB + tx];
        #pragma unroll
        for (int cc = 0; cc < 4; ++cc) {
            unsigned long long wd = bcast2(wr[32 * cc]);
            fma2(acc[0][cc], a01.x, wd);
            fma2(acc[1][cc], a01.y, wd);
            fma2(acc[2][cc], a23.x, wd);
            fma2(acc[3][cc], a23.y, wd);
        }
    }

    // LeakyReLU + store h^T
    #pragma unroll
    for (int cc = 0; cc < 4; ++cc) {
        int c = tx + 32 * cc;
        #pragma unroll
        for (int j = 0; j < 4; ++j) {
            float v0, v1;
            unpack2(acc[j][cc], v0, v1);
            v0 = (v0 >= 0.f) ? v0 : 0.01f * v0;
            v1 = (v1 >= 0.f) ? v1 : 0.01f * v1;
            *reinterpret_cast<unsigned long long*>(&Hs[c * AS_STRIDE + ty * 8 + 2 * j])
                = pack2(v0, v1);
        }
    }
    __syncthreads();

    // Phase 2: out = h @ W2 + b2
    #pragma unroll
    for (int cc = 0; cc < 4; ++cc) {
        unsigned long long bb = bcast2(b2[tx + 32 * cc]);
        #pragma unroll
        for (int j = 0; j < 4; ++j) acc[j][cc] = bb;
    }
    #pragma unroll 4
    for (int k = 0; k < NODE_EMB; ++k) {
        const float* ar = &Hs[k * AS_STRIDE + ty * 8];
        ulonglong2 a01 = *reinterpret_cast<const ulonglong2*>(ar);
        ulonglong2 a23 = *reinterpret_cast<const ulonglong2*>(ar + 4);
        const float* wr = &W2s[k * NODE_EMB + tx];
        #pragma unroll
        for (int cc = 0; cc < 4; ++cc) {
            unsigned long long wd = bcast2(wr[32 * cc]);
            fma2(acc[0][cc], a01.x, wd);
            fma2(acc[1][cc], a01.y, wd);
            fma2(acc[2][cc], a23.x, wd);
            fma2(acc[3][cc], a23.y, wd);
        }
    }

    #pragma unroll
    for (int j = 0; j < 4; ++j) {
        int n0i = node0 + ty * 8 + 2 * j;
        #pragma unroll
        for (int cc = 0; cc < 4; ++cc) {
            float v0, v1;
            unpack2(acc[j][cc], v0, v1);
            int c = tx + 32 * cc;
            if (n0i < N)     out[(size_t)n0i * NODE_EMB + c]       = v0;
            if (n0i + 1 < N) out[(size_t)(n0i + 1) * NODE_EMB + c] = v1;
        }
    }
}

// ---------------- launch ----------------
extern "C" void kernel_launch(void* const* d_in, const int* in_sizes, int n_in,
                              void* d_out, int out_size) {
    const float* x          = (const float*)d_in[0];
    const int*   edge_index = (const int*)  d_in[1];
    const float* edge_attr  = (const float*)d_in[2];
    const float* W1         = (const float*)d_in[3];
    const float* b1         = (const float*)d_in[4];
    const float* W2         = (const float*)d_in[5];
    const float* b2         = (const float*)d_in[6];
    float* out = (float*)d_out;

    int N = in_sizes[0] / NODE_EMB;
    int E = in_sizes[2] / EDGE_EMB;
    int np = (N + TILE_N - 1) / TILE_N;

    zero_kernel<<<1184, 256>>>(N);

    const int fused_smem = (NODE_EMB * AS_STRIDE + NODE_EMB * NODE_EMB) * 4;   // 133120
    cudaFuncSetAttribute(fused_kernel, cudaFuncAttributeMaxDynamicSharedMemorySize, fused_smem);
    fused_kernel<<<NSC + np, THREADS, fused_smem>>>(
        x, edge_index, reinterpret_cast<const float4*>(edge_attr), W1, b1, E, N);

    const int fin_smem = (NODE_EMB * AS_STRIDE + 2 * EDGE_EMB * AS_STRIDE
                          + 2 * EDGE_EMB * NODE_EMB + NODE_EMB * NODE_EMB) * 4; // 166400
    cudaFuncSetAttribute(finish_kernel, cudaFuncAttributeMaxDynamicSharedMemorySize, fin_smem);
    finish_kernel<<<np, THREADS, fin_smem>>>(W1, W2, b2, out, N);
}

// round 7
// speedup vs baseline: 1.2341x; 1.0521x over previous
#include <cuda_runtime.h>
#include <cstdint>

#define NODE_EMB 128
#define EDGE_EMB 16
#define D_IN     160
#define N_MAX    100000
#define TILE_N   128
#define THREADS  512
#define AS_STRIDE 132
#define NSC      100         // scatter CTAs inside fused kernel
#define GRID_F   148         // one CTA per SM, persistent

// ---------------- device scratch ----------------
__device__ float g_rec [N_MAX * EDGE_EMB];
__device__ float g_sent[N_MAX * EDGE_EMB];
__device__ float g_rcnt[N_MAX];
__device__ float g_scnt[N_MAX];
__device__ float g_hp  [N_MAX * NODE_EMB];   // partial h = x@W1a + b1

// ---------------- packed f32x2 helpers ----------------
__device__ __forceinline__ unsigned long long pack2(float lo, float hi) {
    unsigned long long r;
    asm("mov.b64 %0, {%1, %2};" : "=l"(r) : "f"(lo), "f"(hi));
    return r;
}
__device__ __forceinline__ unsigned long long bcast2(float v) {
    unsigned long long r;
    asm("mov.b64 %0, {%1, %1};" : "=l"(r) : "f"(v));
    return r;
}
__device__ __forceinline__ void fma2(unsigned long long& d,
                                     unsigned long long a,
                                     unsigned long long b) {
    asm("fma.rn.f32x2 %0, %1, %2, %0;" : "+l"(d) : "l"(a), "l"(b));
}
__device__ __forceinline__ void unpack2(unsigned long long v, float& lo, float& hi) {
    asm("mov.b64 {%0, %1}, %2;" : "=f"(lo), "=f"(hi) : "l"(v));
}
__device__ __forceinline__ void red4(float* p, float4 v) {
    asm volatile("red.global.add.v4.f32 [%0], {%1, %2, %3, %4};"
                 :: "l"(p), "f"(v.x), "f"(v.y), "f"(v.z), "f"(v.w) : "memory");
}

// ---------------- kernel 1: zero accumulators ----------------
__global__ void zero_kernel(int N) {
    int stride = gridDim.x * blockDim.x;
    int t = blockIdx.x * blockDim.x + threadIdx.x;
    int total4 = N * EDGE_EMB / 4;
    float4 z = make_float4(0.f, 0.f, 0.f, 0.f);
    for (int i = t; i < total4; i += stride) {
        reinterpret_cast<float4*>(g_rec)[i]  = z;
        reinterpret_cast<float4*>(g_sent)[i] = z;
    }
    for (int i = t; i < N; i += stride) {
        g_rcnt[i] = 0.f;
        g_scnt[i] = 0.f;
    }
}

// ---------------- per-edge scatter body ----------------
__device__ __forceinline__ void scatter_edge(int row, int col,
                                             float4 v0, float4 v1,
                                             float4 v2, float4 v3) {
    float* pr = &g_rec [(size_t)row * EDGE_EMB];
    float* ps = &g_sent[(size_t)col * EDGE_EMB];
    red4(pr + 0, v0); red4(pr + 4, v1); red4(pr + 8, v2); red4(pr + 12, v3);
    red4(ps + 0, v0); red4(ps + 4, v1); red4(ps + 8, v2); red4(ps + 12, v3);
    atomicAdd(&g_rcnt[row], 1.0f);
    atomicAdd(&g_scnt[col], 1.0f);
}

// ---------------- kernel 2: heterogeneous scatter + persistent partial-MLP ----------------
// blockIdx < NSC: grid-stride dual scatter-sum (L2-ALU floor ~240us, needs ~96 SMs of issue)
// blockIdx >= NSC: persistent CTA looping node tiles: hp = x @ W1[0:128] + b1.
// Weights loaded ONCE per CTA; runs hidden under the scatter.
__global__ __launch_bounds__(THREADS, 1)
void fused_kernel(const float* __restrict__ x,
                  const int* __restrict__ ei,
                  const float4* __restrict__ attr4,
                  const float* __restrict__ W1,
                  const float* __restrict__ b1,
                  int E, int N, int np) {
    if (blockIdx.x < NSC) {
        int t = blockIdx.x * THREADS + threadIdx.x;
        int stride = NSC * THREADS;
        int e = t;
        // 2-edge ILP main loop
        for (; e + stride < E; e += 2 * stride) {
            int eb = e + stride;
            int r0 = ei[e],      c0 = ei[E + e];
            int r1 = ei[eb],     c1 = ei[E + eb];
            float4 a0 = attr4[(size_t)e * 4 + 0];
            float4 a1 = attr4[(size_t)e * 4 + 1];
            float4 a2 = attr4[(size_t)e * 4 + 2];
            float4 a3 = attr4[(size_t)e * 4 + 3];
            float4 b0 = attr4[(size_t)eb * 4 + 0];
            float4 b1v = attr4[(size_t)eb * 4 + 1];
            float4 b2 = attr4[(size_t)eb * 4 + 2];
            float4 b3 = attr4[(size_t)eb * 4 + 3];
            scatter_edge(r0, c0, a0, a1, a2, a3);
            scatter_edge(r1, c1, b0, b1v, b2, b3);
        }
        if (e < E) {
            int r0 = ei[e], c0 = ei[E + e];
            scatter_edge(r0, c0,
                         attr4[(size_t)e * 4 + 0], attr4[(size_t)e * 4 + 1],
                         attr4[(size_t)e * 4 + 2], attr4[(size_t)e * 4 + 3]);
        }
        return;
    }

    // ---- persistent partial MLP ----
    extern __shared__ float smem_f[];
    float* As  = smem_f;                          // x^T [128][AS_STRIDE]
    float* W1s = As + NODE_EMB * AS_STRIDE;       // W1 rows 0..127 [128][128]

    int tid = threadIdx.x;
    int tx = tid & 31;
    int ty = tid >> 5;

    for (int i = tid; i < (NODE_EMB * NODE_EMB) / 4; i += THREADS)
        reinterpret_cast<float4*>(W1s)[i] = reinterpret_cast<const float4*>(W1)[i];

    unsigned long long bias[4];
    #pragma unroll
    for (int cc = 0; cc < 4; ++cc) bias[cc] = bcast2(b1[tx + 32 * cc]);

    const int nmlp = GRID_F - NSC;
    for (int tile = blockIdx.x - NSC; tile < np; tile += nmlp) {
        int node0 = tile * TILE_N;
        __syncthreads();   // prior iteration's reads of As done
        for (int idx = tid; idx < TILE_N * NODE_EMB; idx += THREADS) {
            int nl = idx >> 7;
            int k  = idx & 127;
            int n  = node0 + nl;
            As[k * AS_STRIDE + nl] = (n < N) ? x[(size_t)n * NODE_EMB + k] : 0.f;
        }
        __syncthreads();

        unsigned long long acc[4][4];
        #pragma unroll
        for (int cc = 0; cc < 4; ++cc) {
            #pragma unroll
            for (int j = 0; j < 4; ++j) acc[j][cc] = bias[cc];
        }
        #pragma unroll 4
        for (int k = 0; k < NODE_EMB; ++k) {
            const float* ar = &As[k * AS_STRIDE + ty * 8];
            ulonglong2 a01 = *reinterpret_cast<const ulonglong2*>(ar);
            ulonglong2 a23 = *reinterpret_cast<const ulonglong2*>(ar + 4);
            const float* wr = &W1s[k * NODE_EMB + tx];
            #pragma unroll
            for (int cc = 0; cc < 4; ++cc) {
                unsigned long long wd = bcast2(wr[32 * cc]);
                fma2(acc[0][cc], a01.x, wd);
                fma2(acc[1][cc], a01.y, wd);
                fma2(acc[2][cc], a23.x, wd);
                fma2(acc[3][cc], a23.y, wd);
            }
        }

        #pragma unroll
        for (int j = 0; j < 4; ++j) {
            int n0i = node0 + ty * 8 + 2 * j;
            #pragma unroll
            for (int cc = 0; cc < 4; ++cc) {
                float v0, v1;
                unpack2(acc[j][cc], v0, v1);
                int c = tx + 32 * cc;
                if (n0i < N)     g_hp[(size_t)n0i * NODE_EMB + c]       = v0;
                if (n0i + 1 < N) g_hp[(size_t)(n0i + 1) * NODE_EMB + c] = v1;
            }
        }
    }
}

// ---------------- kernel 3: persistent finish ----------------
__global__ __launch_bounds__(THREADS, 1)
void finish_kernel(const float* __restrict__ W1,
                   const float* __restrict__ W2,
                   const float* __restrict__ b2,
                   float* __restrict__ out,
                   int N, int np) {
    extern __shared__ float smem_f[];
    float* Hs   = smem_f;                              // h^T [128][AS_STRIDE]
    float* Ms   = Hs + NODE_EMB * AS_STRIDE;           // means^T [32][AS_STRIDE]
    float* W1bs = Ms + 2 * EDGE_EMB * AS_STRIDE;       // W1 rows 128..159
    float* W2s  = W1bs + 2 * EDGE_EMB * NODE_EMB;      // [128][128]

    int tid = threadIdx.x;
    int tx = tid & 31;
    int ty = tid >> 5;

    for (int i = tid; i < (2 * EDGE_EMB * NODE_EMB) / 4; i += THREADS)
        reinterpret_cast<float4*>(W1bs)[i] =
            reinterpret_cast<const float4*>(W1 + NODE_EMB * NODE_EMB)[i];
    for (int i = tid; i < (NODE_EMB * NODE_EMB) / 4; i += THREADS)
        reinterpret_cast<float4*>(W2s)[i] = reinterpret_cast<const float4*>(W2)[i];

    unsigned long long bias2[4];
    #pragma unroll
    for (int cc = 0; cc < 4; ++cc) bias2[cc] = bcast2(b2[tx + 32 * cc]);

    for (int tile = blockIdx.x; tile < np; tile += gridDim.x) {
        int node0 = tile * TILE_N;
        __syncthreads();   // prior tile's reads of Hs/Ms done

        for (int idx = tid; idx < TILE_N * 2 * EDGE_EMB; idx += THREADS) {
            int nl = idx >> 5;
            int k  = idx & 31;
            int n  = node0 + nl;
            float v = 0.f;
            if (n < N) {
                if (k < EDGE_EMB) v = g_rec [(size_t)n * EDGE_EMB + k]              / fmaxf(g_rcnt[n], 1.f);
                else              v = g_sent[(size_t)n * EDGE_EMB + (k - EDGE_EMB)] / fmaxf(g_scnt[n], 1.f);
            }
            Ms[k * AS_STRIDE + nl] = v;
        }
        __syncthreads();

        unsigned long long acc[4][4];
        #pragma unroll
        for (int j = 0; j < 4; ++j) {
            int n0i = node0 + ty * 8 + 2 * j;
            #pragma unroll
            for (int cc = 0; cc < 4; ++cc) {
                int c = tx + 32 * cc;
                float lo = (n0i < N)     ? g_hp[(size_t)n0i * NODE_EMB + c]       : 0.f;
                float hi = (n0i + 1 < N) ? g_hp[(size_t)(n0i + 1) * NODE_EMB + c] : 0.f;
                acc[j][cc] = pack2(lo, hi);
            }
        }

        #pragma unroll 4
        for (int k = 0; k < 2 * EDGE_EMB; ++k) {
            const float* ar = &Ms[k * AS_STRIDE + ty * 8];
            ulonglong2 a01 = *reinterpret_cast<const ulonglong2*>(ar);
            ulonglong2 a23 = *reinterpret_cast<const ulonglong2*>(ar + 4);
            const float* wr = &W1bs[k * NODE_EMB + tx];
            #pragma unroll
            for (int cc = 0; cc < 4; ++cc) {
                unsigned long long wd = bcast2(wr[32 * cc]);
                fma2(acc[0][cc], a01.x, wd);
                fma2(acc[1][cc], a01.y, wd);
                fma2(acc[2][cc], a23.x, wd);
                fma2(acc[3][cc], a23.y, wd);
            }
        }

        #pragma unroll
        for (int cc = 0; cc < 4; ++cc) {
            int c = tx + 32 * cc;
            #pragma unroll
            for (int j = 0; j < 4; ++j) {
                float v0, v1;
                unpack2(acc[j][cc], v0, v1);
                v0 = (v0 >= 0.f) ? v0 : 0.01f * v0;
                v1 = (v1 >= 0.f) ? v1 : 0.01f * v1;
                *reinterpret_cast<unsigned long long*>(&Hs[c * AS_STRIDE + ty * 8 + 2 * j])
                    = pack2(v0, v1);
            }
        }
        __syncthreads();

        #pragma unroll
        for (int cc = 0; cc < 4; ++cc) {
            #pragma unroll
            for (int j = 0; j < 4; ++j) acc[j][cc] = bias2[cc];
        }
        #pragma unroll 4
        for (int k = 0; k < NODE_EMB; ++k) {
            const float* ar = &Hs[k * AS_STRIDE + ty * 8];
            ulonglong2 a01 = *reinterpret_cast<const ulonglong2*>(ar);
            ulonglong2 a23 = *reinterpret_cast<const ulonglong2*>(ar + 4);
            const float* wr = &W2s[k * NODE_EMB + tx];
            #pragma unroll
            for (int cc = 0; cc < 4; ++cc) {
                unsigned long long wd = bcast2(wr[32 * cc]);
                fma2(acc[0][cc], a01.x, wd);
                fma2(acc[1][cc], a01.y, wd);
                fma2(acc[2][cc], a23.x, wd);
                fma2(acc[3][cc], a23.y, wd);
            }
        }

        #pragma unroll
        for (int j = 0; j < 4; ++j) {
            int n0i = node0 + ty * 8 + 2 * j;
            #pragma unroll
            for (int cc = 0; cc < 4; ++cc) {
                float v0, v1;
                unpack2(acc[j][cc], v0, v1);
                int c = tx + 32 * cc;
                if (n0i < N)     out[(size_t)n0i * NODE_EMB + c]       = v0;
                if (n0i + 1 < N) out[(size_t)(n0i + 1) * NODE_EMB + c] = v1;
            }
        }
    }
}

// ---------------- launch ----------------
extern "C" void kernel_launch(void* const* d_in, const int* in_sizes, int n_in,
                              void* d_out, int out_size) {
    const float* x          = (const float*)d_in[0];
    const int*   edge_index = (const int*)  d_in[1];
    const float* edge_attr  = (const float*)d_in[2];
    const float* W1         = (const float*)d_in[3];
    const float* b1         = (const float*)d_in[4];
    const float* W2         = (const float*)d_in[5];
    const float* b2         = (const float*)d_in[6];
    float* out = (float*)d_out;

    int N = in_sizes[0] / NODE_EMB;
    int E = in_sizes[2] / EDGE_EMB;
    int np = (N + TILE_N - 1) / TILE_N;

    zero_kernel<<<1184, 256>>>(N);

    const int fused_smem = (NODE_EMB * AS_STRIDE + NODE_EMB * NODE_EMB) * 4;   // 133120
    cudaFuncSetAttribute(fused_kernel, cudaFuncAttributeMaxDynamicSharedMemorySize, fused_smem);
    fused_kernel<<<GRID_F, THREADS, fused_smem>>>(
        x, edge_index, reinterpret_cast<const float4*>(edge_attr), W1, b1, E, N, np);

    const int fin_smem = (NODE_EMB * AS_STRIDE + 2 * EDGE_EMB * AS_STRIDE
                          + 2 * EDGE_EMB * NODE_EMB + NODE_EMB * NODE_EMB) * 4; // 166400
    cudaFuncSetAttribute(finish_kernel, cudaFuncAttributeMaxDynamicSharedMemorySize, fin_smem);
    finish_kernel<<<GRID_F, THREADS, fin_smem>>>(W1, W2, b2, out, N, np);
}

// round 8
// speedup vs baseline: 1.3083x; 1.0601x over previous
#include <cuda_runtime.h>
#include <cstdint>

#define NODE_EMB 128
#define EDGE_EMB 16
#define D_IN     160
#define N_MAX    100000
#define TILE_N   128
#define THREADS  512
#define AS_STRIDE 132
#define NSC      96          // scatter CTAs inside fused kernel
#define GRID_F   148
#define SLOT_F   20          // floats per staging slot (80B: 16B-aligned, conflict-free STS.128)

// ---------------- device scratch ----------------
__device__ float g_rec [N_MAX * EDGE_EMB];
__device__ float g_sent[N_MAX * EDGE_EMB];
__device__ float g_rcnt[N_MAX];
__device__ float g_scnt[N_MAX];
__device__ float g_hp  [N_MAX * NODE_EMB];   // partial h = x@W1a + b1

// ---------------- packed f32x2 helpers ----------------
__device__ __forceinline__ unsigned long long pack2(float lo, float hi) {
    unsigned long long r;
    asm("mov.b64 %0, {%1, %2};" : "=l"(r) : "f"(lo), "f"(hi));
    return r;
}
__device__ __forceinline__ unsigned long long bcast2(float v) {
    unsigned long long r;
    asm("mov.b64 %0, {%1, %1};" : "=l"(r) : "f"(v));
    return r;
}
__device__ __forceinline__ void fma2(unsigned long long& d,
                                     unsigned long long a,
                                     unsigned long long b) {
    asm("fma.rn.f32x2 %0, %1, %2, %0;" : "+l"(d) : "l"(a), "l"(b));
}
__device__ __forceinline__ void unpack2(unsigned long long v, float& lo, float& hi) {
    asm("mov.b64 {%0, %1}, %2;" : "=f"(lo), "=f"(hi) : "l"(v));
}

// ---------------- kernel 1: zero accumulators ----------------
__global__ void zero_kernel(int N) {
    int stride = gridDim.x * blockDim.x;
    int t = blockIdx.x * blockDim.x + threadIdx.x;
    int total4 = N * EDGE_EMB / 4;
    float4 z = make_float4(0.f, 0.f, 0.f, 0.f);
    for (int i = t; i < total4; i += stride) {
        reinterpret_cast<float4*>(g_rec)[i]  = z;
        reinterpret_cast<float4*>(g_sent)[i] = z;
    }
    for (int i = t; i < N; i += stride) {
        g_rcnt[i] = 0.f;
        g_scnt[i] = 0.f;
    }
}

// ---------------- kernel 2: heterogeneous bulk-scatter + persistent partial-MLP ----------------
// blockIdx < NSC: grid-stride dual scatter via cp.reduce.async.bulk (low SM issue,
//   stays at the L2-atomic-ALU floor ~240us even on 96 SMs).
// blockIdx >= NSC: persistent partial MLP hp = x @ W1[0:128] + b1 (hidden under scatter).
__global__ __launch_bounds__(THREADS, 1)
void fused_kernel(const float* __restrict__ x,
                  const int* __restrict__ ei,
                  const float4* __restrict__ attr4,
                  const float* __restrict__ W1,
                  const float* __restrict__ b1,
                  int E, int N, int np) {
    extern __shared__ float smem_f[];

    if (blockIdx.x < NSC) {
        // Staging: 2 slots x 512 threads x SLOT_F floats (80KB)
        int tid = threadIdx.x;
        int t = blockIdx.x * THREADS + tid;
        int stride = NSC * THREADS;
        int it = 0;
        for (int e = t; e < E; e += stride, ++it) {
            float* sl = smem_f + (size_t)(it & 1) * (THREADS * SLOT_F) + tid * SLOT_F;
            // Slot reuse safety: allow at most 1 pending bulk group (the other slot's)
            asm volatile("cp.async.bulk.wait_group 1;" ::: "memory");
            float4* sv = reinterpret_cast<float4*>(sl);
            sv[0] = attr4[(size_t)e * 4 + 0];
            sv[1] = attr4[(size_t)e * 4 + 1];
            sv[2] = attr4[(size_t)e * 4 + 2];
            sv[3] = attr4[(size_t)e * 4 + 3];
            int row = ei[e];
            int col = ei[E + e];
            asm volatile("fence.proxy.async.shared::cta;" ::: "memory");
            uint32_t src;
            asm("{ .reg .u64 tt; cvta.to.shared.u64 tt, %1; cvt.u32.u64 %0, tt; }"
                : "=r"(src) : "l"((const void*)sl));
            float* pr = &g_rec [(size_t)row * EDGE_EMB];
            float* ps = &g_sent[(size_t)col * EDGE_EMB];
            asm volatile(
                "cp.reduce.async.bulk.global.shared::cta.bulk_group.add.f32 [%0], [%1], 64;"
                :: "l"(pr), "r"(src) : "memory");
            asm volatile(
                "cp.reduce.async.bulk.global.shared::cta.bulk_group.add.f32 [%0], [%1], 64;"
                :: "l"(ps), "r"(src) : "memory");
            atomicAdd(&g_rcnt[row], 1.0f);
            atomicAdd(&g_scnt[col], 1.0f);
            asm volatile("cp.async.bulk.commit_group;" ::: "memory");
        }
        asm volatile("cp.async.bulk.wait_group 0;" ::: "memory");
        return;
    }

    // ---- persistent partial MLP ----
    float* As  = smem_f;                          // x^T [128][AS_STRIDE]
    float* W1s = As + NODE_EMB * AS_STRIDE;       // W1 rows 0..127 [128][128]

    int tid = threadIdx.x;
    int tx = tid & 31;
    int ty = tid >> 5;

    for (int i = tid; i < (NODE_EMB * NODE_EMB) / 4; i += THREADS)
        reinterpret_cast<float4*>(W1s)[i] = reinterpret_cast<const float4*>(W1)[i];

    unsigned long long bias[4];
    #pragma unroll
    for (int cc = 0; cc < 4; ++cc) bias[cc] = bcast2(b1[tx + 32 * cc]);

    const int nmlp = GRID_F - NSC;
    for (int tile = blockIdx.x - NSC; tile < np; tile += nmlp) {
        int node0 = tile * TILE_N;
        __syncthreads();
        for (int idx = tid; idx < TILE_N * NODE_EMB; idx += THREADS) {
            int nl = idx >> 7;
            int k  = idx & 127;
            int n  = node0 + nl;
            As[k * AS_STRIDE + nl] = (n < N) ? x[(size_t)n * NODE_EMB + k] : 0.f;
        }
        __syncthreads();

        unsigned long long acc[4][4];
        #pragma unroll
        for (int cc = 0; cc < 4; ++cc) {
            #pragma unroll
            for (int j = 0; j < 4; ++j) acc[j][cc] = bias[cc];
        }
        #pragma unroll 4
        for (int k = 0; k < NODE_EMB; ++k) {
            const float* ar = &As[k * AS_STRIDE + ty * 8];
            ulonglong2 a01 = *reinterpret_cast<const ulonglong2*>(ar);
            ulonglong2 a23 = *reinterpret_cast<const ulonglong2*>(ar + 4);
            const float* wr = &W1s[k * NODE_EMB + tx];
            #pragma unroll
            for (int cc = 0; cc < 4; ++cc) {
                unsigned long long wd = bcast2(wr[32 * cc]);
                fma2(acc[0][cc], a01.x, wd);
                fma2(acc[1][cc], a01.y, wd);
                fma2(acc[2][cc], a23.x, wd);
                fma2(acc[3][cc], a23.y, wd);
            }
        }

        #pragma unroll
        for (int j = 0; j < 4; ++j) {
            int n0i = node0 + ty * 8 + 2 * j;
            #pragma unroll
            for (int cc = 0; cc < 4; ++cc) {
                float v0, v1;
                unpack2(acc[j][cc], v0, v1);
                int c = tx + 32 * cc;
                if (n0i < N)     g_hp[(size_t)n0i * NODE_EMB + c]       = v0;
                if (n0i + 1 < N) g_hp[(size_t)(n0i + 1) * NODE_EMB + c] = v1;
            }
        }
    }
}

// ---------------- kernel 3: persistent finish ----------------
__global__ __launch_bounds__(THREADS, 1)
void finish_kernel(const float* __restrict__ W1,
                   const float* __restrict__ W2,
                   const float* __restrict__ b2,
                   float* __restrict__ out,
                   int N, int np) {
    extern __shared__ float smem_f[];
    float* Hs   = smem_f;                              // h^T [128][AS_STRIDE]
    float* Ms   = Hs + NODE_EMB * AS_STRIDE;           // means^T [32][AS_STRIDE]
    float* W1bs = Ms + 2 * EDGE_EMB * AS_STRIDE;       // W1 rows 128..159
    float* W2s  = W1bs + 2 * EDGE_EMB * NODE_EMB;      // [128][128]

    int tid = threadIdx.x;
    int tx = tid & 31;
    int ty = tid >> 5;

    for (int i = tid; i < (2 * EDGE_EMB * NODE_EMB) / 4; i += THREADS)
        reinterpret_cast<float4*>(W1bs)[i] =
            reinterpret_cast<const float4*>(W1 + NODE_EMB * NODE_EMB)[i];
    for (int i = tid; i < (NODE_EMB * NODE_EMB) / 4; i += THREADS)
        reinterpret_cast<float4*>(W2s)[i] = reinterpret_cast<const float4*>(W2)[i];

    unsigned long long bias2[4];
    #pragma unroll
    for (int cc = 0; cc < 4; ++cc) bias2[cc] = bcast2(b2[tx + 32 * cc]);

    for (int tile = blockIdx.x; tile < np; tile += gridDim.x) {
        int node0 = tile * TILE_N;
        __syncthreads();

        for (int idx = tid; idx < TILE_N * 2 * EDGE_EMB; idx += THREADS) {
            int nl = idx >> 5;
            int k  = idx & 31;
            int n  = node0 + nl;
            float v = 0.f;
            if (n < N) {
                if (k < EDGE_EMB) v = g_rec [(size_t)n * EDGE_EMB + k]              / fmaxf(g_rcnt[n], 1.f);
                else              v = g_sent[(size_t)n * EDGE_EMB + (k - EDGE_EMB)] / fmaxf(g_scnt[n], 1.f);
            }
            Ms[k * AS_STRIDE + nl] = v;
        }
        __syncthreads();

        unsigned long long acc[4][4];
        #pragma unroll
        for (int j = 0; j < 4; ++j) {
            int n0i = node0 + ty * 8 + 2 * j;
            #pragma unroll
            for (int cc = 0; cc < 4; ++cc) {
                int c = tx + 32 * cc;
                float lo = (n0i < N)     ? g_hp[(size_t)n0i * NODE_EMB + c]       : 0.f;
                float hi = (n0i + 1 < N) ? g_hp[(size_t)(n0i + 1) * NODE_EMB + c] : 0.f;
                acc[j][cc] = pack2(lo, hi);
            }
        }

        #pragma unroll 4
        for (int k = 0; k < 2 * EDGE_EMB; ++k) {
            const float* ar = &Ms[k * AS_STRIDE + ty * 8];
            ulonglong2 a01 = *reinterpret_cast<const ulonglong2*>(ar);
            ulonglong2 a23 = *reinterpret_cast<const ulonglong2*>(ar + 4);
            const float* wr = &W1bs[k * NODE_EMB + tx];
            #pragma unroll
            for (int cc = 0; cc < 4; ++cc) {
                unsigned long long wd = bcast2(wr[32 * cc]);
                fma2(acc[0][cc], a01.x, wd);
                fma2(acc[1][cc], a01.y, wd);
                fma2(acc[2][cc], a23.x, wd);
                fma2(acc[3][cc], a23.y, wd);
            }
        }

        #pragma unroll
        for (int cc = 0; cc < 4; ++cc) {
            int c = tx + 32 * cc;
            #pragma unroll
            for (int j = 0; j < 4; ++j) {
                float v0, v1;
                unpack2(acc[j][cc], v0, v1);
                v0 = (v0 >= 0.f) ? v0 : 0.01f * v0;
                v1 = (v1 >= 0.f) ? v1 : 0.01f * v1;
                *reinterpret_cast<unsigned long long*>(&Hs[c * AS_STRIDE + ty * 8 + 2 * j])
                    = pack2(v0, v1);
            }
        }
        __syncthreads();

        #pragma unroll
        for (int cc = 0; cc < 4; ++cc) {
            #pragma unroll
            for (int j = 0; j < 4; ++j) acc[j][cc] = bias2[cc];
        }
        #pragma unroll 4
        for (int k = 0; k < NODE_EMB; ++k) {
            const float* ar = &Hs[k * AS_STRIDE + ty * 8];
            ulonglong2 a01 = *reinterpret_cast<const ulonglong2*>(ar);
            ulonglong2 a23 = *reinterpret_cast<const ulonglong2*>(ar + 4);
            const float* wr = &W2s[k * NODE_EMB + tx];
            #pragma unroll
            for (int cc = 0; cc < 4; ++cc) {
                unsigned long long wd = bcast2(wr[32 * cc]);
                fma2(acc[0][cc], a01.x, wd);
                fma2(acc[1][cc], a01.y, wd);
                fma2(acc[2][cc], a23.x, wd);
                fma2(acc[3][cc], a23.y, wd);
            }
        }

        #pragma unroll
        for (int j = 0; j < 4; ++j) {
            int n0i = node0 + ty * 8 + 2 * j;
            #pragma unroll
            for (int cc = 0; cc < 4; ++cc) {
                float v0, v1;
                unpack2(acc[j][cc], v0, v1);
                int c = tx + 32 * cc;
                if (n0i < N)     out[(size_t)n0i * NODE_EMB + c]       = v0;
                if (n0i + 1 < N) out[(size_t)(n0i + 1) * NODE_EMB + c] = v1;
            }
        }
    }
}

// ---------------- launch ----------------
extern "C" void kernel_launch(void* const* d_in, const int* in_sizes, int n_in,
                              void* d_out, int out_size) {
    const float* x          = (const float*)d_in[0];
    const int*   edge_index = (const int*)  d_in[1];
    const float* edge_attr  = (const float*)d_in[2];
    const float* W1         = (const float*)d_in[3];
    const float* b1         = (const float*)d_in[4];
    const float* W2         = (const float*)d_in[5];
    const float* b2         = (const float*)d_in[6];
    float* out = (float*)d_out;

    int N = in_sizes[0] / NODE_EMB;
    int E = in_sizes[2] / EDGE_EMB;
    int np = (N + TILE_N - 1) / TILE_N;

    zero_kernel<<<1184, 256>>>(N);

    // smem: max(MLP: A^T + W1a = 133120B, scatter: 2*512*20*4 = 81920B)
    const int fused_smem = (NODE_EMB * AS_STRIDE + NODE_EMB * NODE_EMB) * 4;   // 133120
    cudaFuncSetAttribute(fused_kernel, cudaFuncAttributeMaxDynamicSharedMemorySize, fused_smem);
    fused_kernel<<<GRID_F, THREADS, fused_smem>>>(
        x, edge_index, reinterpret_cast<const float4*>(edge_attr), W1, b1, E, N, np);

    const int fin_smem = (NODE_EMB * AS_STRIDE + 2 * EDGE_EMB * AS_STRIDE
                          + 2 * EDGE_EMB * NODE_EMB + NODE_EMB * NODE_EMB) * 4; // 166400
    cudaFuncSetAttribute(finish_kernel, cudaFuncAttributeMaxDynamicSharedMemorySize, fin_smem);
    finish_kernel<<<GRID_F, THREADS, fin_smem>>>(W1, W2, b2, out, N, np);
}

// round 10
// speedup vs baseline: 1.3885x; 1.0613x over previous
#include <cuda_runtime.h>
#include <cstdint>

#define NODE_EMB 128
#define EDGE_EMB 16
#define D_IN     160      // 128 + 2*16
#define N_MAX    100000

#define TILE_N   128
#define THREADS  512
#define AS_STRIDE 132     // padded: 16B-aligned rows, 4-way-max staging conflicts
#define GRID_MLP 148

// Scratch: scatter-mean accumulators (device globals — no cudaMalloc allowed)
__device__ float g_rec [N_MAX * EDGE_EMB];
__device__ float g_sent[N_MAX * EDGE_EMB];
__device__ float g_rcnt[N_MAX];
__device__ float g_scnt[N_MAX];

// ---------------- packed f32x2 helpers (sm_100+) ----------------
__device__ __forceinline__ unsigned long long pack2(float lo, float hi) {
    unsigned long long r;
    asm("mov.b64 %0, {%1, %2};" : "=l"(r) : "f"(lo), "f"(hi));
    return r;
}
__device__ __forceinline__ unsigned long long bcast2(float v) {
    unsigned long long r;
    asm("mov.b64 %0, {%1, %1};" : "=l"(r) : "f"(v));
    return r;
}
__device__ __forceinline__ void fma2(unsigned long long& d,
                                     unsigned long long a,
                                     unsigned long long b) {
    asm("fma.rn.f32x2 %0, %1, %2, %0;" : "+l"(d) : "l"(a), "l"(b));
}
__device__ __forceinline__ void unpack2(unsigned long long v, float& lo, float& hi) {
    asm("mov.b64 {%0, %1}, %2;" : "=f"(lo), "=f"(hi) : "l"(v));
}

// ---------------- kernel 1: zero accumulators ----------------
__global__ void zero_kernel(int N) {
    int stride = gridDim.x * blockDim.x;
    int t = blockIdx.x * blockDim.x + threadIdx.x;
    int total4 = N * EDGE_EMB / 4;
    float4 z = make_float4(0.f, 0.f, 0.f, 0.f);
    for (int i = t; i < total4; i += stride) {
        reinterpret_cast<float4*>(g_rec)[i]  = z;
        reinterpret_cast<float4*>(g_sent)[i] = z;
    }
    for (int i = t; i < N; i += stride) {
        g_rcnt[i] = 0.f;
        g_scnt[i] = 0.f;
    }
}

// ---------------- kernel 2: fused dual scatter-sum (R4 proven form) ----------------
// At full grid this sits at the L2 sector-RMW floor (~243us) — measured path-independent.
__global__ void scatter_kernel(const float4* __restrict__ edge_attr4,
                               const int* __restrict__ edge_index,
                               int E) {
    int t = blockIdx.x * blockDim.x + threadIdx.x;
    int total = E * 4;
    if (t >= total) return;
    int e = t >> 2;
    int q = t & 3;
    float4 v = edge_attr4[t];
    int row = edge_index[e];        // receiver
    int col = edge_index[E + e];    // sender
    float* pr = &g_rec [row * EDGE_EMB + q * 4];
    float* ps = &g_sent[col * EDGE_EMB + q * 4];
    asm volatile("red.global.add.v4.f32 [%0], {%1, %2, %3, %4};"
                 :: "l"(pr), "f"(v.x), "f"(v.y), "f"(v.z), "f"(v.w) : "memory");
    asm volatile("red.global.add.v4.f32 [%0], {%1, %2, %3, %4};"
                 :: "l"(ps), "f"(v.x), "f"(v.y), "f"(v.z), "f"(v.w) : "memory");
    if (q == 0) {
        atomicAdd(&g_rcnt[row], 1.0f);
        atomicAdd(&g_scnt[col], 1.0f);
    }
}

// ---------------- kernel 3: persistent fused concat + MLP ----------------
// 148 CTAs x 512 threads, grid-stride over 128-node tiles. Weights/biases loaded ONCE.
// Inner scheme = R4 (transposed-A node-pair, FFMA2-throughput-bound).
__global__ __launch_bounds__(THREADS, 1)
void mlp_kernel(const float* __restrict__ x,
                const float* __restrict__ W1,
                const float* __restrict__ b1,
                const float* __restrict__ W2,
                const float* __restrict__ b2,
                float* __restrict__ out,
                int N, int np) {
    extern __shared__ float smem_f[];
    float* As  = smem_f;                        // [D_IN][AS_STRIDE] transposed A / h
    float* W1s = As + D_IN * AS_STRIDE;         // [160][128]
    float* W2s = W1s + D_IN * NODE_EMB;         // [128][128]

    int tid = threadIdx.x;
    int tx = tid & 31;
    int ty = tid >> 5;

    // Weights loaded once per CTA (persistent)
    for (int i = tid; i < (D_IN * NODE_EMB) / 4; i += THREADS)
        reinterpret_cast<float4*>(W1s)[i] = reinterpret_cast<const float4*>(W1)[i];
    for (int i = tid; i < (NODE_EMB * NODE_EMB) / 4; i += THREADS)
        reinterpret_cast<float4*>(W2s)[i] = reinterpret_cast<const float4*>(W2)[i];

    unsigned long long bias1[4], bias2[4];
    #pragma unroll
    for (int cc = 0; cc < 4; ++cc) {
        bias1[cc] = bcast2(b1[tx + 32 * cc]);
        bias2[cc] = bcast2(b2[tx + 32 * cc]);
    }

    for (int tile = blockIdx.x; tile < np; tile += GRID_MLP) {
        int node0 = tile * TILE_N;
        __syncthreads();   // previous tile's reads of As complete

        // Stage A^T: concat(x, rec_mean, sent_mean), transposed [k][node]
        for (int idx = tid; idx < TILE_N * D_IN; idx += THREADS) {
            int nl = idx / D_IN;
            int k  = idx - nl * D_IN;
            int n  = node0 + nl;
            float v = 0.f;
            if (n < N) {
                if (k < NODE_EMB) {
                    v = x[(size_t)n * NODE_EMB + k];
                } else if (k < NODE_EMB + EDGE_EMB) {
                    float c = g_rcnt[n];
                    v = g_rec[n * EDGE_EMB + (k - NODE_EMB)] / fmaxf(c, 1.f);
                } else {
                    float c = g_scnt[n];
                    v = g_sent[n * EDGE_EMB + (k - NODE_EMB - EDGE_EMB)] / fmaxf(c, 1.f);
                }
            }
            As[k * AS_STRIDE + nl] = v;
        }
        __syncthreads();

        // ---- Phase 1: h = A @ W1 + b1 ----
        unsigned long long acc[4][4];   // [node-pair j][col cc]
        #pragma unroll
        for (int cc = 0; cc < 4; ++cc) {
            #pragma unroll
            for (int j = 0; j < 4; ++j) acc[j][cc] = bias1[cc];
        }
        #pragma unroll 4
        for (int k = 0; k < D_IN; ++k) {
            const float* ar = &As[k * AS_STRIDE + ty * 8];
            ulonglong2 a01 = *reinterpret_cast<const ulonglong2*>(ar);      // nodes 0-3
            ulonglong2 a23 = *reinterpret_cast<const ulonglong2*>(ar + 4);  // nodes 4-7
            const float* wr = &W1s[k * NODE_EMB + tx];
            #pragma unroll
            for (int cc = 0; cc < 4; ++cc) {
                unsigned long long wd = bcast2(wr[32 * cc]);
                fma2(acc[0][cc], a01.x, wd);
                fma2(acc[1][cc], a01.y, wd);
                fma2(acc[2][cc], a23.x, wd);
                fma2(acc[3][cc], a23.y, wd);
            }
        }
        __syncthreads();   // all reads of As done before overwrite

        // LeakyReLU + store h^T[c][node]
        #pragma unroll
        for (int cc = 0; cc < 4; ++cc) {
            int c = tx + 32 * cc;
            #pragma unroll
            for (int j = 0; j < 4; ++j) {
                float v0, v1;
                unpack2(acc[j][cc], v0, v1);
                v0 = (v0 >= 0.f) ? v0 : 0.01f * v0;
                v1 = (v1 >= 0.f) ? v1 : 0.01f * v1;
                *reinterpret_cast<unsigned long long*>(&As[c * AS_STRIDE + ty * 8 + 2 * j])
                    = pack2(v0, v1);
            }
        }
        __syncthreads();

        // ---- Phase 2: out = h @ W2 + b2 ----
        #pragma unroll
        for (int cc = 0; cc < 4; ++cc) {
            #pragma unroll
            for (int j = 0; j < 4; ++j) acc[j][cc] = bias2[cc];
        }
        #pragma unroll 4
        for (int k = 0; k < NODE_EMB; ++k) {
            const float* ar = &As[k * AS_STRIDE + ty * 8];
            ulonglong2 a01 = *reinterpret_cast<const ulonglong2*>(ar);
            ulonglong2 a23 = *reinterpret_cast<const ulonglong2*>(ar + 4);
            const float* wr = &W2s[k * NODE_EMB + tx];
            #pragma unroll
            for (int cc = 0; cc < 4; ++cc) {
                unsigned long long wd = bcast2(wr[32 * cc]);
                fma2(acc[0][cc], a01.x, wd);
                fma2(acc[1][cc], a01.y, wd);
                fma2(acc[2][cc], a23.x, wd);
                fma2(acc[3][cc], a23.y, wd);
            }
        }

        // Store out[n][c]
        #pragma unroll
        for (int j = 0; j < 4; ++j) {
            int n0i = node0 + ty * 8 + 2 * j;
            #pragma unroll
            for (int cc = 0; cc < 4; ++cc) {
                float v0, v1;
                unpack2(acc[j][cc], v0, v1);
                int c = tx + 32 * cc;
                if (n0i < N)     out[(size_t)n0i * NODE_EMB + c]       = v0;
                if (n0i + 1 < N) out[(size_t)(n0i + 1) * NODE_EMB + c] = v1;
            }
        }
    }
}

// ---------------- launch ----------------
extern "C" void kernel_launch(void* const* d_in, const int* in_sizes, int n_in,
                              void* d_out, int out_size) {
    const float* x          = (const float*)d_in[0];
    const int*   edge_index = (const int*)  d_in[1];
    const float* edge_attr  = (const float*)d_in[2];
    const float* W1         = (const float*)d_in[3];
    const float* b1         = (const float*)d_in[4];
    const float* W2         = (const float*)d_in[5];
    const float* b2         = (const float*)d_in[6];
    float* out = (float*)d_out;

    int N = in_sizes[0] / NODE_EMB;
    int E = in_sizes[2] / EDGE_EMB;
    int np = (N + TILE_N - 1) / TILE_N;

    zero_kernel<<<1184, 256>>>(N);

    int total = E * 4;
    scatter_kernel<<<(total + 255) / 256, 256>>>(
        reinterpret_cast<const float4*>(edge_attr), edge_index, E);

    const int smem_bytes = (D_IN * AS_STRIDE + D_IN * NODE_EMB + NODE_EMB * NODE_EMB) * 4; // 231936
    cudaFuncSetAttribute(mlp_kernel, cudaFuncAttributeMaxDynamicSharedMemorySize, smem_bytes);
    mlp_kernel<<<GRID_MLP, THREADS, smem_bytes>>>(
        x, W1, b1, W2, b2, out, N, np);
}